// round 1
// baseline (speedup 1.0000x reference)
#include <cuda_runtime.h>
#include <math.h>

#define H 1024
#define V 50257
#define L 2

// Scratch (no allocations allowed)
__device__ float g_x[H];        // current layer input
__device__ float g_logits[V];   // raw logits
__device__ float g_red[2];      // max, log(sumexp)

__device__ __forceinline__ float warp_sum(float s) {
    #pragma unroll
    for (int o = 16; o > 0; o >>= 1) s += __shfl_xor_sync(0xFFFFFFFF, s, o);
    return s;
}

__device__ __forceinline__ float sigmoidf_(float v) {
    return 1.0f / (1.0f + __expf(-v));
}

// ---- 1. embedding lookup + ReLU -> g_x ----
__global__ void embed_relu_kernel(const long long* __restrict__ idx,
                                  const float* __restrict__ emb) {
    int j = threadIdx.x;
    long long t = idx[0];
    float v = emb[t * (long long)H + j];
    g_x[j] = v > 0.0f ? v : 0.0f;
}

// ---- 2/3. one GRU layer. grid = H blocks, 192 threads (6 warps). ----
// Warp w in [0,3): dot(w_ih[row], x);  w in [3,6): dot(w_hh[row], h_prev)
// row = (w % 3) * H + j
__global__ __launch_bounds__(192) void gru_layer_kernel(
    const float* __restrict__ h_prev,   // [H]
    const float* __restrict__ w_ih,     // [3H, H]
    const float* __restrict__ w_hh,     // [3H, H]
    const float* __restrict__ b_ih,     // [3H]
    const float* __restrict__ b_hh,     // [3H]
    float* __restrict__ h_out_scratch,  // g_x (feeds next layer)
    float* __restrict__ h_out_final)    // d_out slice for this layer
{
    int j = blockIdx.x;
    int w = threadIdx.x >> 5;
    int lane = threadIdx.x & 31;

    const float* vec = (w < 3) ? g_x : h_prev;
    const float* W   = (w < 3) ? w_ih : w_hh;
    int row = (w % 3) * H + j;

    const float4* wr = reinterpret_cast<const float4*>(W + (size_t)row * H);
    const float4* vv = reinterpret_cast<const float4*>(vec);

    float s = 0.0f;
    #pragma unroll 4
    for (int i = lane; i < H / 4; i += 32) {
        float4 a = wr[i];
        float4 b = vv[i];
        s += a.x * b.x + a.y * b.y + a.z * b.z + a.w * b.w;
    }
    s = warp_sum(s);

    __shared__ float sm[6];
    if (lane == 0) sm[w] = s;
    __syncthreads();

    if (threadIdx.x == 0) {
        float i_r = sm[0] + b_ih[j];
        float i_z = sm[1] + b_ih[H + j];
        float i_n = sm[2] + b_ih[2 * H + j];
        float h_r = sm[3] + b_hh[j];
        float h_z = sm[4] + b_hh[H + j];
        float h_n = sm[5] + b_hh[2 * H + j];
        float r = sigmoidf_(i_r + h_r);
        float z = sigmoidf_(i_z + h_z);
        float n = tanhf(i_n + r * h_n);
        float hn = (1.0f - z) * n + z * h_prev[j];
        h_out_scratch[j] = hn;
        h_out_final[j]   = hn;
    }
}

// ---- 4. logits = w_out @ x + b_out. 8 warps/block, 1 warp per row. ----
__global__ __launch_bounds__(256) void logits_kernel(
    const float* __restrict__ w_out,  // [V, H]
    const float* __restrict__ b_out)  // [V]
{
    __shared__ float xs[H];
    for (int i = threadIdx.x; i < H; i += 256) xs[i] = g_x[i];
    __syncthreads();

    int row = blockIdx.x * 8 + (threadIdx.x >> 5);
    if (row >= V) return;
    int lane = threadIdx.x & 31;

    const float4* wr = reinterpret_cast<const float4*>(w_out + (size_t)row * H);
    const float4* vv = reinterpret_cast<const float4*>(xs);

    float s = 0.0f;
    #pragma unroll 4
    for (int i = lane; i < H / 4; i += 32) {
        float4 a = wr[i];
        float4 b = vv[i];
        s += a.x * b.x + a.y * b.y + a.z * b.z + a.w * b.w;
    }
    s = warp_sum(s);
    if (lane == 0) g_logits[row] = s + b_out[row];
}

// ---- 5. log_softmax: single block, 3 passes over L2-resident logits ----
__global__ __launch_bounds__(1024) void logsoftmax_kernel(float* __restrict__ out) {
    __shared__ float red[32];
    int tid = threadIdx.x;
    int lane = tid & 31;
    int wid = tid >> 5;

    // pass 1: max
    float m = -INFINITY;
    for (int i = tid; i < V; i += 1024) m = fmaxf(m, g_logits[i]);
    #pragma unroll
    for (int o = 16; o > 0; o >>= 1) m = fmaxf(m, __shfl_xor_sync(0xFFFFFFFF, m, o));
    if (lane == 0) red[wid] = m;
    __syncthreads();
    if (tid < 32) {
        float v = red[tid];
        #pragma unroll
        for (int o = 16; o > 0; o >>= 1) v = fmaxf(v, __shfl_xor_sync(0xFFFFFFFF, v, o));
        if (tid == 0) red[0] = v;
    }
    __syncthreads();
    float gmax = red[0];
    __syncthreads();

    // pass 2: sum exp
    float s = 0.0f;
    for (int i = tid; i < V; i += 1024) s += expf(g_logits[i] - gmax);
    s = warp_sum(s);
    if (lane == 0) red[wid] = s;
    __syncthreads();
    if (tid < 32) {
        float v = red[tid];
        v = warp_sum(v);
        if (tid == 0) red[0] = logf(v);
    }
    __syncthreads();
    float lse = red[0];

    // pass 3: write logprobs
    float c = gmax + lse;
    for (int i = tid; i < V; i += 1024) out[i] = g_logits[i] - c;
}

extern "C" void kernel_launch(void* const* d_in, const int* in_sizes, int n_in,
                              void* d_out, int out_size) {
    // metadata order:
    // 0 input (int64,1), 1 hidden (L,1,H), 2 emb (V,H), 3 w_ih (L,3H,H),
    // 4 w_hh (L,3H,H), 5 b_ih (L,3H), 6 b_hh (L,3H), 7 w_out (V,H), 8 b_out (V)
    const long long* idx  = (const long long*)d_in[0];
    const float* hidden   = (const float*)d_in[1];
    const float* emb      = (const float*)d_in[2];
    const float* w_ih     = (const float*)d_in[3];
    const float* w_hh     = (const float*)d_in[4];
    const float* b_ih     = (const float*)d_in[5];
    const float* b_hh     = (const float*)d_in[6];
    const float* w_out    = (const float*)d_in[7];
    const float* b_out    = (const float*)d_in[8];

    float* out = (float*)d_out;
    float* out_logprobs = out;            // [V]
    float* out_hidden   = out + V;        // [L, 1, H]

    float* g_x_ptr;
    cudaGetSymbolAddress((void**)&g_x_ptr, g_x);

    // 1. embed + relu
    embed_relu_kernel<<<1, H>>>(idx, emb);

    // 2. GRU layer 0 (input = g_x, h = hidden[0])
    gru_layer_kernel<<<H, 192>>>(hidden,
                                 w_ih, w_hh, b_ih, b_hh,
                                 g_x_ptr, out_hidden);

    // 3. GRU layer 1 (input = g_x = h0_new, h = hidden[1])
    gru_layer_kernel<<<H, 192>>>(hidden + H,
                                 w_ih + 3 * H * H, w_hh + 3 * H * H,
                                 b_ih + 3 * H, b_hh + 3 * H,
                                 g_x_ptr, out_hidden + H);

    // 4. vocab projection
    logits_kernel<<<(V + 7) / 8, 256>>>(w_out, b_out);

    // 5. log_softmax -> d_out[0:V]
    logsoftmax_kernel<<<1, 1024>>>(out_logprobs);
}

// round 2
// speedup vs baseline: 1.1416x; 1.1416x over previous
#include <cuda_runtime.h>
#include <math.h>

#define H 1024
#define V 50257
#define L 2
#define LOGITS_ROWS_PER_BLOCK 8
#define NB_LOGITS ((V + LOGITS_ROWS_PER_BLOCK - 1) / LOGITS_ROWS_PER_BLOCK)  // 6283

// Scratch (device globals; no allocation allowed)
__device__ float g_x[H];              // GRU layer 0 output
__device__ float g_y[H];              // GRU layer 1 output (logits input)
__device__ float g_logits[V];
__device__ float g_pmax[NB_LOGITS];   // per-block online-softmax partials
__device__ float g_psum[NB_LOGITS];
__device__ float g_c[1];              // max + log(sumexp)

__device__ __forceinline__ float warp_sum(float s) {
    #pragma unroll
    for (int o = 16; o > 0; o >>= 1) s += __shfl_xor_sync(0xFFFFFFFF, s, o);
    return s;
}
__device__ __forceinline__ float warp_max(float s) {
    #pragma unroll
    for (int o = 16; o > 0; o >>= 1) s = fmaxf(s, __shfl_xor_sync(0xFFFFFFFF, s, o));
    return s;
}
__device__ __forceinline__ float sigmoidf_(float v) {
    return 1.0f / (1.0f + __expf(-v));
}

// ---- GRU layer. grid = H blocks, 192 threads (6 warps). ----
// Warp w in [0,3): dot(w_ih[(w%3)*H+j], x);  w in [3,6): dot(w_hh[...], h_prev)
// FUSE_EMB: x[i] = relu(emb[idx[0]*H + i]) computed inline.
template<bool FUSE_EMB>
__global__ __launch_bounds__(192) void gru_layer_kernel(
    const long long* __restrict__ idx,
    const float* __restrict__ emb,
    const float* __restrict__ x_vec,    // input activation (ignored if FUSE_EMB)
    const float* __restrict__ h_prev,   // [H]
    const float* __restrict__ w_ih,     // [3H, H]
    const float* __restrict__ w_hh,     // [3H, H]
    const float* __restrict__ b_ih,     // [3H]
    const float* __restrict__ b_hh,     // [3H]
    float* __restrict__ h_out_scratch,  // feeds next stage
    float* __restrict__ h_out_final)    // d_out slice for this layer
{
    int j = blockIdx.x;
    int w = threadIdx.x >> 5;
    int lane = threadIdx.x & 31;

    const float* vec;
    bool do_relu = false;
    if (w < 3) {
        if (FUSE_EMB) { vec = emb + (size_t)idx[0] * H; do_relu = true; }
        else          { vec = x_vec; }
    } else {
        vec = h_prev;
    }
    const float* W = (w < 3) ? w_ih : w_hh;
    int row = (w % 3) * H + j;

    const float4* wr = reinterpret_cast<const float4*>(W + (size_t)row * H);
    const float4* vv = reinterpret_cast<const float4*>(vec);

    // 8 independent 16B loads per operand -> MLP 8+
    float4 a[8], b[8];
    #pragma unroll
    for (int k = 0; k < 8; k++) a[k] = __ldcs(&wr[lane + 32 * k]);
    #pragma unroll
    for (int k = 0; k < 8; k++) b[k] = __ldg(&vv[lane + 32 * k]);
    if (do_relu) {
        #pragma unroll
        for (int k = 0; k < 8; k++) {
            b[k].x = fmaxf(b[k].x, 0.0f); b[k].y = fmaxf(b[k].y, 0.0f);
            b[k].z = fmaxf(b[k].z, 0.0f); b[k].w = fmaxf(b[k].w, 0.0f);
        }
    }
    float s = 0.0f;
    #pragma unroll
    for (int k = 0; k < 8; k++)
        s += a[k].x * b[k].x + a[k].y * b[k].y + a[k].z * b[k].z + a[k].w * b[k].w;
    s = warp_sum(s);

    __shared__ float sm[6];
    if (lane == 0) sm[w] = s;
    __syncthreads();

    if (threadIdx.x == 0) {
        float i_r = sm[0] + b_ih[j];
        float i_z = sm[1] + b_ih[H + j];
        float i_n = sm[2] + b_ih[2 * H + j];
        float h_r = sm[3] + b_hh[j];
        float h_z = sm[4] + b_hh[H + j];
        float h_n = sm[5] + b_hh[2 * H + j];
        float r = sigmoidf_(i_r + h_r);
        float z = sigmoidf_(i_z + h_z);
        float n = tanhf(i_n + r * h_n);
        float hn = (1.0f - z) * n + z * h_prev[j];
        h_out_scratch[j] = hn;
        h_out_final[j]   = hn;
    }
}

// ---- logits = w_out @ y + b_out, with per-block online-softmax partials ----
__global__ __launch_bounds__(256) void logits_kernel(
    const float* __restrict__ w_out,  // [V, H]
    const float* __restrict__ b_out)  // [V]
{
    __shared__ float xs[H];
    __shared__ float rowv[LOGITS_ROWS_PER_BLOCK];
    for (int i = threadIdx.x; i < H; i += 256) xs[i] = g_y[i];
    __syncthreads();

    int wid = threadIdx.x >> 5;
    int lane = threadIdx.x & 31;
    int row = blockIdx.x * LOGITS_ROWS_PER_BLOCK + wid;

    float val = -INFINITY;
    if (row < V) {
        const float4* wr = reinterpret_cast<const float4*>(w_out + (size_t)row * H);
        const float4* vv = reinterpret_cast<const float4*>(xs);

        float4 a[8];
        #pragma unroll
        for (int k = 0; k < 8; k++) a[k] = __ldcs(&wr[lane + 32 * k]);
        float s = 0.0f;
        #pragma unroll
        for (int k = 0; k < 8; k++) {
            float4 b = vv[lane + 32 * k];
            s += a[k].x * b.x + a[k].y * b.y + a[k].z * b.z + a[k].w * b.w;
        }
        s = warp_sum(s);
        if (lane == 0) {
            val = s + b_out[row];
            g_logits[row] = val;
        }
    }
    if (lane == 0) rowv[wid] = val;
    __syncthreads();

    // thread 0: block-local online softmax partial over up to 8 rows
    if (threadIdx.x == 0) {
        float m = -INFINITY;
        #pragma unroll
        for (int k = 0; k < LOGITS_ROWS_PER_BLOCK; k++) m = fmaxf(m, rowv[k]);
        float sum = 0.0f;
        #pragma unroll
        for (int k = 0; k < LOGITS_ROWS_PER_BLOCK; k++) {
            float v = rowv[k];
            if (v != -INFINITY) sum += expf(v - m);
        }
        g_pmax[blockIdx.x] = m;
        g_psum[blockIdx.x] = sum;
    }
}

// ---- combine partials: c = gmax + log( sum_b psum_b * exp(pmax_b - gmax) ) ----
__global__ __launch_bounds__(1024) void reduce_kernel() {
    __shared__ float red[32];
    int tid = threadIdx.x;
    int lane = tid & 31;
    int wid = tid >> 5;

    float m = -INFINITY;
    for (int i = tid; i < NB_LOGITS; i += 1024) m = fmaxf(m, g_pmax[i]);
    m = warp_max(m);
    if (lane == 0) red[wid] = m;
    __syncthreads();
    if (tid < 32) {
        float v = red[tid];
        v = warp_max(v);
        if (tid == 0) red[0] = v;
    }
    __syncthreads();
    float gmax = red[0];
    __syncthreads();

    float s = 0.0f;
    for (int i = tid; i < NB_LOGITS; i += 1024)
        s += g_psum[i] * expf(g_pmax[i] - gmax);
    s = warp_sum(s);
    if (lane == 0) red[wid] = s;
    __syncthreads();
    if (tid < 32) {
        float v = red[tid];
        v = warp_sum(v);
        if (tid == 0) g_c[0] = gmax + logf(v);
    }
}

// ---- write logprobs: out[i] = logits[i] - c (wide, L2-resident) ----
__global__ __launch_bounds__(512) void write_kernel(float* __restrict__ out) {
    int i = blockIdx.x * 512 + threadIdx.x;
    if (i < V) out[i] = g_logits[i] - g_c[0];
}

extern "C" void kernel_launch(void* const* d_in, const int* in_sizes, int n_in,
                              void* d_out, int out_size) {
    const long long* idx  = (const long long*)d_in[0];
    const float* hidden   = (const float*)d_in[1];
    const float* emb      = (const float*)d_in[2];
    const float* w_ih     = (const float*)d_in[3];
    const float* w_hh     = (const float*)d_in[4];
    const float* b_ih     = (const float*)d_in[5];
    const float* b_hh     = (const float*)d_in[6];
    const float* w_out    = (const float*)d_in[7];
    const float* b_out    = (const float*)d_in[8];

    float* out = (float*)d_out;
    float* out_logprobs = out;       // [V]
    float* out_hidden   = out + V;   // [L, 1, H]

    float* g_x_ptr; cudaGetSymbolAddress((void**)&g_x_ptr, g_x);
    float* g_y_ptr; cudaGetSymbolAddress((void**)&g_y_ptr, g_y);

    // GRU layer 0 (embed+relu fused), writes g_x
    gru_layer_kernel<true><<<H, 192>>>(idx, emb, nullptr, hidden,
                                       w_ih, w_hh, b_ih, b_hh,
                                       g_x_ptr, out_hidden);

    // GRU layer 1: reads g_x, writes g_y (no aliasing race)
    gru_layer_kernel<false><<<H, 192>>>(idx, emb, g_x_ptr, hidden + H,
                                        w_ih + 3 * H * H, w_hh + 3 * H * H,
                                        b_ih + 3 * H, b_hh + 3 * H,
                                        g_y_ptr, out_hidden + H);

    // vocab projection + online-softmax partials
    logits_kernel<<<NB_LOGITS, 256>>>(w_out, b_out);

    // combine partials
    reduce_kernel<<<1, 1024>>>();

    // final logprobs
    write_kernel<<<(V + 511) / 512, 512>>>(out_logprobs);
}